// round 6
// baseline (speedup 1.0000x reference)
#include <cuda_runtime.h>

// Chamfer distance, B=8, Np=8192, Ng=8192, D=3.
// f32x2 packed FMAs; +1.0 bias makes all distances positive so float bits
// order as integers -> 3-input integer min (vmin3) everywhere, no f2o.

#define BB 8
#define NN 8192
#define THREADS 128
#define RR 8                        // pred points per thread (4 packed pairs)
#define RP (RR / 2)
#define TILE_P (THREADS * RR)       // 1024 pred points per block
#define PBLK (NN / TILE_P)          // 8
#define SPLIT_G 16
#define CHUNK_G (NN / SPLIT_G)      // 512 gt points per block
#define NWARP (THREADS / 32)        // 4

// Privatized partial minima (plain stores; every slot written, no init).
__device__ float g_minp_part[SPLIT_G][BB * NN];
__device__ float g_ming_part[PBLK][BB * NN];
__device__ double g_partial[128];

// ---- packed f32x2 helpers ----
__device__ __forceinline__ unsigned long long add2(unsigned long long a, unsigned long long b) {
    unsigned long long d;
    asm("add.rn.f32x2 %0, %1, %2;" : "=l"(d) : "l"(a), "l"(b));
    return d;
}
__device__ __forceinline__ unsigned long long fma2(unsigned long long a, unsigned long long b,
                                                   unsigned long long c) {
    unsigned long long d;
    asm("fma.rn.f32x2 %0, %1, %2, %3;" : "=l"(d) : "l"(a), "l"(b), "l"(c));
    return d;
}
__device__ __forceinline__ unsigned long long pack2(float lo, float hi) {
    unsigned long long d;
    asm("mov.b64 %0, {%1, %2};" : "=l"(d) : "f"(lo), "f"(hi));
    return d;
}
__device__ __forceinline__ void unpack2i(int& lo, int& hi, unsigned long long a) {
    asm("mov.b64 {%0, %1}, %2;" : "=r"(lo), "=r"(hi) : "l"(a));
}
// 3-input integer min: d = min(min(a,b), c). Valid for positive-float bits.
__device__ __forceinline__ int vmin3(int a, int b, int c) {
    int d;
    asm("vmin.s32.s32.s32.min %0, %1, %2, %3;" : "=r"(d) : "r"(a), "r"(b), "r"(c));
    return d;
}
__device__ __forceinline__ int redux_min_s32(int v) {
    int d;
    asm("redux.sync.min.s32 %0, %1, %2;" : "=r"(d) : "r"(v), "r"(0xFFFFFFFFu));
    return d;
}

#define POS_INF_BITS 0x7F800000

__global__ __launch_bounds__(THREADS, 8)
void chamfer_main(const float* __restrict__ pred, const float* __restrict__ gt) {
    const int bs = blockIdx.x;          // [0, BB*PBLK)
    const int b  = bs / PBLK;
    const int pb = bs % PBLK;
    const int gs = blockIdx.y;          // [0, SPLIT_G)
    const int tid = threadIdx.x;
    const int lane = tid & 31;
    const int warp = tid >> 5;

    // Duplicated-lane packed gt: shga[j]={-2x,-2x,-2y,-2y},
    // shgb[j]={-2z,-2z,g2+1,g2+1}  (+1 bias keeps all distances positive).
    __shared__ float4 shga[CHUNK_G];
    __shared__ float4 shgb[CHUNK_G];
    __shared__ int    shminw[NWARP][CHUNK_G];   // per-warp min (biased float bits)

    const float* gtb = gt + ((long)b * NN + (long)gs * CHUNK_G) * 3;
    for (int j = tid; j < CHUNK_G; j += THREADS) {
        float x = gtb[j * 3 + 0];
        float y = gtb[j * 3 + 1];
        float z = gtb[j * 3 + 2];
        float nx = -2.0f * x, ny = -2.0f * y, nz = -2.0f * z;
        float w = x * x + y * y + z * z + 1.0f;
        shga[j] = make_float4(nx, nx, ny, ny);
        shgb[j] = make_float4(nz, nz, w, w);
    }

    // RR pred points per thread, packed in pairs.
    unsigned long long px2[RP], py2[RP], pz2[RP], pw2[RP];
    int mp[RR];                              // biased distance bits, per pred point
    const float* pbase = pred + ((long)b * NN + (long)pb * TILE_P) * 3;
#pragma unroll
    for (int p = 0; p < RP; p++) {
        int i0 = (2 * p) * THREADS + tid;
        int i1 = (2 * p + 1) * THREADS + tid;
        float x0 = pbase[i0 * 3 + 0], y0 = pbase[i0 * 3 + 1], z0 = pbase[i0 * 3 + 2];
        float x1 = pbase[i1 * 3 + 0], y1 = pbase[i1 * 3 + 1], z1 = pbase[i1 * 3 + 2];
        px2[p] = pack2(x0, x1);
        py2[p] = pack2(y0, y1);
        pz2[p] = pack2(z0, z1);
        pw2[p] = pack2(x0 * x0 + y0 * y0 + z0 * z0,
                       x1 * x1 + y1 * y1 + z1 * z1);
        mp[2 * p]     = POS_INF_BITS;
        mp[2 * p + 1] = POS_INF_BITS;
    }
    __syncthreads();

    const ulonglong2* ga = reinterpret_cast<const ulonglong2*>(shga);
    const ulonglong2* gb = reinterpret_cast<const ulonglong2*>(shgb);

#pragma unroll 2
    for (int j = 0; j < CHUNK_G; j += 2) {
        ulonglong2 A0 = ga[j],     B0 = gb[j];
        ulonglong2 A1 = ga[j + 1], B1 = gb[j + 1];

        int l0[8], l1[8];   // biased distance bits: [2p]=lo, [2p+1]=hi
#pragma unroll
        for (int p = 0; p < RP; p++) {
            unsigned long long a = add2(pw2[p], B0.y);   // p^2 + g^2 + 1
            a = fma2(A0.x, px2[p], a);
            a = fma2(A0.y, py2[p], a);
            a = fma2(B0.x, pz2[p], a);
            unpack2i(l0[2 * p], l0[2 * p + 1], a);

            unsigned long long c = add2(pw2[p], B1.y);
            c = fma2(A1.x, px2[p], c);
            c = fma2(A1.y, py2[p], c);
            c = fma2(B1.x, pz2[p], c);
            unpack2i(l1[2 * p], l1[2 * p + 1], c);
        }
        // pred-direction: fold both j's into the accumulator (1 vmin3 each).
#pragma unroll
        for (int r = 0; r < RR; r++)
            mp[r] = vmin3(mp[r], l0[r], l1[r]);

        // gt-direction: 8-leaf min trees via vmin3 (4 ops each).
        int v1 = vmin3(l0[0], l0[1], l0[2]);
        int v2 = vmin3(l0[3], l0[4], l0[5]);
        int v3 = vmin3(l0[6], l0[7], v1);
        int m0 = min(v2, v3);
        int w1 = vmin3(l1[0], l1[1], l1[2]);
        int w2 = vmin3(l1[3], l1[4], l1[5]);
        int w3 = vmin3(l1[6], l1[7], w1);
        int m1 = min(w2, w3);

        m0 = redux_min_s32(m0);
        m1 = redux_min_s32(m1);
        if (lane == 0) {
            shminw[warp][j]     = m0;
            shminw[warp][j + 1] = m1;
        }
    }
    __syncthreads();

    // gt-direction publish: combine warps (integer min), unbias, plain store.
    float* gm = g_ming_part[pb] + (long)b * NN + (long)gs * CHUNK_G;
    for (int j = tid; j < CHUNK_G; j += THREADS) {
        int v = shminw[0][j];
#pragma unroll
        for (int w = 1; w < NWARP; w++) v = min(v, shminw[w][j]);
        gm[j] = __int_as_float(v) - 1.0f;
    }

    // pred-direction publish: unbias, plain store to this gs's slice.
    float* pm = g_minp_part[gs] + (long)b * NN + (long)pb * TILE_P;
#pragma unroll
    for (int r = 0; r < RR; r++)
        pm[r * THREADS + tid] = __int_as_float(mp[r]) - 1.0f;
}

#define F1BLOCKS 128
#define F1T 256
#define PTS_PER_BLK (BB * NN / F1BLOCKS)   // 512

__global__ __launch_bounds__(F1T)
void chamfer_finalize1() {
    __shared__ double sh[F1T];
    const int base = blockIdx.x * PTS_PER_BLK;
    double acc = 0.0;
    for (int i = threadIdx.x; i < PTS_PER_BLK; i += F1T) {
        int idx = base + i;
        float vp = g_minp_part[0][idx];
#pragma unroll
        for (int s = 1; s < SPLIT_G; s++) vp = fminf(vp, g_minp_part[s][idx]);
        float vg = g_ming_part[0][idx];
#pragma unroll
        for (int s = 1; s < PBLK; s++) vg = fminf(vg, g_ming_part[s][idx]);
        acc += (double)vp + (double)vg;
    }
    sh[threadIdx.x] = acc;
    __syncthreads();
    for (int s = F1T / 2; s > 0; s >>= 1) {
        if (threadIdx.x < s) sh[threadIdx.x] += sh[threadIdx.x + s];
        __syncthreads();
    }
    if (threadIdx.x == 0) g_partial[blockIdx.x] = sh[0];
}

__global__ void chamfer_finalize2(float* __restrict__ out) {
    __shared__ double sh[F1BLOCKS];
    sh[threadIdx.x] = g_partial[threadIdx.x];
    __syncthreads();
    for (int s = F1BLOCKS / 2; s > 0; s >>= 1) {
        if (threadIdx.x < s) sh[threadIdx.x] += sh[threadIdx.x + s];
        __syncthreads();
    }
    if (threadIdx.x == 0)
        out[0] = (float)(sh[0] / ((double)NN * (double)BB));
}

extern "C" void kernel_launch(void* const* d_in, const int* in_sizes, int n_in,
                              void* d_out, int out_size) {
    const float* pred = (const float*)d_in[0];
    const float* gt   = (const float*)d_in[1];
    float* out = (float*)d_out;

    dim3 grid(BB * PBLK, SPLIT_G);
    chamfer_main<<<grid, THREADS>>>(pred, gt);
    chamfer_finalize1<<<F1BLOCKS, F1T>>>();
    chamfer_finalize2<<<1, F1BLOCKS>>>(out);
}

// round 8
// speedup vs baseline: 2.8698x; 2.8698x over previous
#include <cuda_runtime.h>

// Chamfer distance, B=8, Np=8192, Ng=8192, D=3.
// f32x2 packed FMAs; +1.0 bias keeps all distances positive so raw float
// bits order as s32 -> redux.sync.min.s32 with no encode/decode.

#define BB 8
#define NN 8192
#define THREADS 128
#define RR 8                        // pred points per thread (4 packed pairs)
#define RP (RR / 2)
#define TILE_P (THREADS * RR)       // 1024 pred points per block
#define PBLK (NN / TILE_P)          // 8
#define SPLIT_G 16
#define CHUNK_G (NN / SPLIT_G)      // 512 gt points per block
#define NWARP (THREADS / 32)        // 4

// Privatized partial minima (plain stores; every slot written, no init).
__device__ float g_minp_part[SPLIT_G][BB * NN];
__device__ float g_ming_part[PBLK][BB * NN];
__device__ double g_partial[128];

// ---- packed f32x2 helpers (pack/unpack movs are register-pair pseudo-ops) ----
__device__ __forceinline__ unsigned long long add2(unsigned long long a, unsigned long long b) {
    unsigned long long d;
    asm("add.rn.f32x2 %0, %1, %2;" : "=l"(d) : "l"(a), "l"(b));
    return d;
}
__device__ __forceinline__ unsigned long long fma2(unsigned long long a, unsigned long long b,
                                                   unsigned long long c) {
    unsigned long long d;
    asm("fma.rn.f32x2 %0, %1, %2, %3;" : "=l"(d) : "l"(a), "l"(b), "l"(c));
    return d;
}
__device__ __forceinline__ unsigned long long pack2(float lo, float hi) {
    unsigned long long d;
    asm("mov.b64 %0, {%1, %2};" : "=l"(d) : "f"(lo), "f"(hi));
    return d;
}
__device__ __forceinline__ void unpack2f(float& lo, float& hi, unsigned long long a) {
    asm("mov.b64 {%0, %1}, %2;" : "=f"(lo), "=f"(hi) : "l"(a));
}
__device__ __forceinline__ int redux_min_s32(int v) {
    int d;
    asm("redux.sync.min.s32 %0, %1, %2;" : "=r"(d) : "r"(v), "r"(0xFFFFFFFFu));
    return d;
}

__global__ __launch_bounds__(THREADS, 8)
void chamfer_main(const float* __restrict__ pred, const float* __restrict__ gt) {
    const int bs = blockIdx.x;          // [0, BB*PBLK)
    const int b  = bs / PBLK;
    const int pb = bs % PBLK;
    const int gs = blockIdx.y;          // [0, SPLIT_G)
    const int tid = threadIdx.x;
    const int lane = tid & 31;
    const int warp = tid >> 5;

    // Duplicated-lane packed gt: shga[j]={-2x,-2x,-2y,-2y},
    // shgb[j]={-2z,-2z,g2+1,g2+1}  (+1 bias keeps all distances positive).
    __shared__ float4 shga[CHUNK_G];
    __shared__ float4 shgb[CHUNK_G];
    __shared__ int    shminw[NWARP][CHUNK_G];   // per-warp min (biased float bits)

    const float* gtb = gt + ((long)b * NN + (long)gs * CHUNK_G) * 3;
    for (int j = tid; j < CHUNK_G; j += THREADS) {
        float x = gtb[j * 3 + 0];
        float y = gtb[j * 3 + 1];
        float z = gtb[j * 3 + 2];
        float nx = -2.0f * x, ny = -2.0f * y, nz = -2.0f * z;
        float w = x * x + y * y + z * z + 1.0f;
        shga[j] = make_float4(nx, nx, ny, ny);
        shgb[j] = make_float4(nz, nz, w, w);
    }

    // RR pred points per thread, packed in pairs.
    unsigned long long px2[RP], py2[RP], pz2[RP], pw2[RP];
    float mp[RR];                        // biased running mins (scalar)
    const float* pbase = pred + ((long)b * NN + (long)pb * TILE_P) * 3;
#pragma unroll
    for (int p = 0; p < RP; p++) {
        int i0 = (2 * p) * THREADS + tid;
        int i1 = (2 * p + 1) * THREADS + tid;
        float x0 = pbase[i0 * 3 + 0], y0 = pbase[i0 * 3 + 1], z0 = pbase[i0 * 3 + 2];
        float x1 = pbase[i1 * 3 + 0], y1 = pbase[i1 * 3 + 1], z1 = pbase[i1 * 3 + 2];
        px2[p] = pack2(x0, x1);
        py2[p] = pack2(y0, y1);
        pz2[p] = pack2(z0, z1);
        pw2[p] = pack2(x0 * x0 + y0 * y0 + z0 * z0,
                       x1 * x1 + y1 * y1 + z1 * z1);
        mp[2 * p]     = __int_as_float(0x7F800000);
        mp[2 * p + 1] = __int_as_float(0x7F800000);
    }
    __syncthreads();

    const ulonglong2* ga = reinterpret_cast<const ulonglong2*>(shga);
    const ulonglong2* gb = reinterpret_cast<const ulonglong2*>(shgb);

#pragma unroll 2
    for (int j = 0; j < CHUNK_G; j += 2) {
        ulonglong2 A0 = ga[j],     B0 = gb[j];
        ulonglong2 A1 = ga[j + 1], B1 = gb[j + 1];

        float m0, m1;
        {
            float tm[RP];
#pragma unroll
            for (int p = 0; p < RP; p++) {
                unsigned long long a = add2(pw2[p], B0.y);   // p^2 + g^2 + 1
                a = fma2(A0.x, px2[p], a);
                a = fma2(A0.y, py2[p], a);
                a = fma2(B0.x, pz2[p], a);
                float lo, hi;
                unpack2f(lo, hi, a);
                mp[2 * p]     = fminf(mp[2 * p], lo);
                mp[2 * p + 1] = fminf(mp[2 * p + 1], hi);
                tm[p] = fminf(lo, hi);
            }
            m0 = fminf(fminf(tm[0], tm[1]), fminf(tm[2], tm[3]));
        }
        {
            float tm[RP];
#pragma unroll
            for (int p = 0; p < RP; p++) {
                unsigned long long a = add2(pw2[p], B1.y);
                a = fma2(A1.x, px2[p], a);
                a = fma2(A1.y, py2[p], a);
                a = fma2(B1.x, pz2[p], a);
                float lo, hi;
                unpack2f(lo, hi, a);
                mp[2 * p]     = fminf(mp[2 * p], lo);
                mp[2 * p + 1] = fminf(mp[2 * p + 1], hi);
                tm[p] = fminf(lo, hi);
            }
            m1 = fminf(fminf(tm[0], tm[1]), fminf(tm[2], tm[3]));
        }
        // Raw-bit integer redux (valid: all values positive).
        int u0 = redux_min_s32(__float_as_int(m0));
        int u1 = redux_min_s32(__float_as_int(m1));
        if (lane == 0) {
            shminw[warp][j]     = u0;
            shminw[warp][j + 1] = u1;
        }
    }
    __syncthreads();

    // gt-direction publish: combine warps (int min on positive bits), unbias.
    float* gm = g_ming_part[pb] + (long)b * NN + (long)gs * CHUNK_G;
    for (int j = tid; j < CHUNK_G; j += THREADS) {
        int v = shminw[0][j];
#pragma unroll
        for (int w = 1; w < NWARP; w++) v = min(v, shminw[w][j]);
        gm[j] = __int_as_float(v) - 1.0f;
    }

    // pred-direction publish: unbias, plain store.
    float* pm = g_minp_part[gs] + (long)b * NN + (long)pb * TILE_P;
#pragma unroll
    for (int r = 0; r < RR; r++)
        pm[r * THREADS + tid] = mp[r] - 1.0f;
}

#define F1BLOCKS 128
#define F1T 256
#define PTS_PER_BLK (BB * NN / F1BLOCKS)   // 512

__global__ __launch_bounds__(F1T)
void chamfer_finalize1() {
    __shared__ double sh[F1T];
    const int base = blockIdx.x * PTS_PER_BLK;
    double acc = 0.0;
    for (int i = threadIdx.x; i < PTS_PER_BLK; i += F1T) {
        int idx = base + i;
        float vp = g_minp_part[0][idx];
#pragma unroll
        for (int s = 1; s < SPLIT_G; s++) vp = fminf(vp, g_minp_part[s][idx]);
        float vg = g_ming_part[0][idx];
#pragma unroll
        for (int s = 1; s < PBLK; s++) vg = fminf(vg, g_ming_part[s][idx]);
        acc += (double)vp + (double)vg;
    }
    sh[threadIdx.x] = acc;
    __syncthreads();
    for (int s = F1T / 2; s > 0; s >>= 1) {
        if (threadIdx.x < s) sh[threadIdx.x] += sh[threadIdx.x + s];
        __syncthreads();
    }
    if (threadIdx.x == 0) g_partial[blockIdx.x] = sh[0];
}

__global__ void chamfer_finalize2(float* __restrict__ out) {
    __shared__ double sh[F1BLOCKS];
    sh[threadIdx.x] = g_partial[threadIdx.x];
    __syncthreads();
    for (int s = F1BLOCKS / 2; s > 0; s >>= 1) {
        if (threadIdx.x < s) sh[threadIdx.x] += sh[threadIdx.x + s];
        __syncthreads();
    }
    if (threadIdx.x == 0)
        out[0] = (float)(sh[0] / ((double)NN * (double)BB));
}

extern "C" void kernel_launch(void* const* d_in, const int* in_sizes, int n_in,
                              void* d_out, int out_size) {
    const float* pred = (const float*)d_in[0];
    const float* gt   = (const float*)d_in[1];
    float* out = (float*)d_out;

    dim3 grid(BB * PBLK, SPLIT_G);
    chamfer_main<<<grid, THREADS>>>(pred, gt);
    chamfer_finalize1<<<F1BLOCKS, F1T>>>();
    chamfer_finalize2<<<1, F1BLOCKS>>>(out);
}

// round 9
// speedup vs baseline: 2.9160x; 1.0161x over previous
#include <cuda_runtime.h>

// Chamfer distance, B=8, Np=8192, Ng=8192, D=3.
// f32x2 packed FMAs; +1.0 bias -> positive distances -> raw-bit s32 redux.
// Branch-free reduction tail: all lanes store redux result (same addr,
// same value, write-combined) as one STS.64 -> no BSSY/BSYNC in hot loop.

#define BB 8
#define NN 8192
#define THREADS 128
#define RR 8                        // pred points per thread (4 packed pairs)
#define RP (RR / 2)
#define TILE_P (THREADS * RR)       // 1024 pred points per block
#define PBLK (NN / TILE_P)          // 8
#define SPLIT_G 16
#define CHUNK_G (NN / SPLIT_G)      // 512 gt points per block
#define NWARP (THREADS / 32)        // 4

// Privatized partial minima (plain stores; every slot written, no init).
__device__ float g_minp_part[SPLIT_G][BB * NN];
__device__ float g_ming_part[PBLK][BB * NN];
__device__ double g_partial[128];

// ---- packed f32x2 helpers (pack/unpack movs are register-pair pseudo-ops) ----
__device__ __forceinline__ unsigned long long add2(unsigned long long a, unsigned long long b) {
    unsigned long long d;
    asm("add.rn.f32x2 %0, %1, %2;" : "=l"(d) : "l"(a), "l"(b));
    return d;
}
__device__ __forceinline__ unsigned long long fma2(unsigned long long a, unsigned long long b,
                                                   unsigned long long c) {
    unsigned long long d;
    asm("fma.rn.f32x2 %0, %1, %2, %3;" : "=l"(d) : "l"(a), "l"(b), "l"(c));
    return d;
}
__device__ __forceinline__ unsigned long long pack2(float lo, float hi) {
    unsigned long long d;
    asm("mov.b64 %0, {%1, %2};" : "=l"(d) : "f"(lo), "f"(hi));
    return d;
}
__device__ __forceinline__ unsigned long long pack2i(int lo, int hi) {
    unsigned long long d;
    asm("mov.b64 %0, {%1, %2};" : "=l"(d) : "r"(lo), "r"(hi));
    return d;
}
__device__ __forceinline__ void unpack2f(float& lo, float& hi, unsigned long long a) {
    asm("mov.b64 {%0, %1}, %2;" : "=f"(lo), "=f"(hi) : "l"(a));
}
__device__ __forceinline__ int redux_min_s32(int v) {
    int d;
    asm("redux.sync.min.s32 %0, %1, %2;" : "=r"(d) : "r"(v), "r"(0xFFFFFFFFu));
    return d;
}

__global__ __launch_bounds__(THREADS, 8)
void chamfer_main(const float* __restrict__ pred, const float* __restrict__ gt) {
    const int bs = blockIdx.x;          // [0, BB*PBLK)
    const int b  = bs / PBLK;
    const int pb = bs % PBLK;
    const int gs = blockIdx.y;          // [0, SPLIT_G)
    const int tid = threadIdx.x;
    const int warp = tid >> 5;

    // Duplicated-lane packed gt: shga[j]={-2x,-2x,-2y,-2y},
    // shgb[j]={-2z,-2z,g2+1,g2+1}  (+1 bias keeps all distances positive).
    __shared__ float4 shga[CHUNK_G];
    __shared__ float4 shgb[CHUNK_G];
    __shared__ unsigned long long shminw2[NWARP][CHUNK_G / 2];  // packed {j, j+1} mins

    const float* gtb = gt + ((long)b * NN + (long)gs * CHUNK_G) * 3;
    for (int j = tid; j < CHUNK_G; j += THREADS) {
        float x = gtb[j * 3 + 0];
        float y = gtb[j * 3 + 1];
        float z = gtb[j * 3 + 2];
        float nx = -2.0f * x, ny = -2.0f * y, nz = -2.0f * z;
        float w = x * x + y * y + z * z + 1.0f;
        shga[j] = make_float4(nx, nx, ny, ny);
        shgb[j] = make_float4(nz, nz, w, w);
    }

    // RR pred points per thread, packed in pairs.
    unsigned long long px2[RP], py2[RP], pz2[RP], pw2[RP];
    float mp[RR];                        // biased running mins (scalar)
    const float* pbase = pred + ((long)b * NN + (long)pb * TILE_P) * 3;
#pragma unroll
    for (int p = 0; p < RP; p++) {
        int i0 = (2 * p) * THREADS + tid;
        int i1 = (2 * p + 1) * THREADS + tid;
        float x0 = pbase[i0 * 3 + 0], y0 = pbase[i0 * 3 + 1], z0 = pbase[i0 * 3 + 2];
        float x1 = pbase[i1 * 3 + 0], y1 = pbase[i1 * 3 + 1], z1 = pbase[i1 * 3 + 2];
        px2[p] = pack2(x0, x1);
        py2[p] = pack2(y0, y1);
        pz2[p] = pack2(z0, z1);
        pw2[p] = pack2(x0 * x0 + y0 * y0 + z0 * z0,
                       x1 * x1 + y1 * y1 + z1 * z1);
        mp[2 * p]     = __int_as_float(0x7F800000);
        mp[2 * p + 1] = __int_as_float(0x7F800000);
    }
    __syncthreads();

    const ulonglong2* ga = reinterpret_cast<const ulonglong2*>(shga);
    const ulonglong2* gb = reinterpret_cast<const ulonglong2*>(shgb);

    for (int j = 0; j < CHUNK_G; j += 2) {
        ulonglong2 A0 = ga[j],     B0 = gb[j];
        ulonglong2 A1 = ga[j + 1], B1 = gb[j + 1];

        float m0, m1;
        {
            float tm[RP];
#pragma unroll
            for (int p = 0; p < RP; p++) {
                unsigned long long a = add2(pw2[p], B0.y);   // p^2 + g^2 + 1
                a = fma2(A0.x, px2[p], a);
                a = fma2(A0.y, py2[p], a);
                a = fma2(B0.x, pz2[p], a);
                float lo, hi;
                unpack2f(lo, hi, a);
                mp[2 * p]     = fminf(mp[2 * p], lo);
                mp[2 * p + 1] = fminf(mp[2 * p + 1], hi);
                tm[p] = fminf(lo, hi);
            }
            m0 = fminf(fminf(tm[0], tm[1]), fminf(tm[2], tm[3]));
        }
        {
            float tm[RP];
#pragma unroll
            for (int p = 0; p < RP; p++) {
                unsigned long long a = add2(pw2[p], B1.y);
                a = fma2(A1.x, px2[p], a);
                a = fma2(A1.y, py2[p], a);
                a = fma2(B1.x, pz2[p], a);
                float lo, hi;
                unpack2f(lo, hi, a);
                mp[2 * p]     = fminf(mp[2 * p], lo);
                mp[2 * p + 1] = fminf(mp[2 * p + 1], hi);
                tm[p] = fminf(lo, hi);
            }
            m1 = fminf(fminf(tm[0], tm[1]), fminf(tm[2], tm[3]));
        }
        // Raw-bit integer redux (valid: all values positive). All lanes get
        // the result; all lanes store the SAME value to the SAME address
        // (write-combined) -> no lane-0 branch, no BSSY/BSYNC.
        int u0 = redux_min_s32(__float_as_int(m0));
        int u1 = redux_min_s32(__float_as_int(m1));
        shminw2[warp][j >> 1] = pack2i(u0, u1);
    }
    __syncthreads();

    // gt-direction publish: combine warps (int min on positive bits), unbias.
    const int* sw = reinterpret_cast<const int*>(shminw2);  // [w][j] int view
    float* gm = g_ming_part[pb] + (long)b * NN + (long)gs * CHUNK_G;
    for (int j = tid; j < CHUNK_G; j += THREADS) {
        int v = sw[j];
#pragma unroll
        for (int w = 1; w < NWARP; w++) v = min(v, sw[w * CHUNK_G + j]);
        gm[j] = __int_as_float(v) - 1.0f;
    }

    // pred-direction publish: unbias, plain store.
    float* pm = g_minp_part[gs] + (long)b * NN + (long)pb * TILE_P;
#pragma unroll
    for (int r = 0; r < RR; r++)
        pm[r * THREADS + tid] = mp[r] - 1.0f;
}

#define F1BLOCKS 128
#define F1T 256
#define PTS_PER_BLK (BB * NN / F1BLOCKS)   // 512

__global__ __launch_bounds__(F1T)
void chamfer_finalize1() {
    __shared__ double sh[F1T];
    const int base = blockIdx.x * PTS_PER_BLK;
    double acc = 0.0;
    for (int i = threadIdx.x; i < PTS_PER_BLK; i += F1T) {
        int idx = base + i;
        float vp = g_minp_part[0][idx];
#pragma unroll
        for (int s = 1; s < SPLIT_G; s++) vp = fminf(vp, g_minp_part[s][idx]);
        float vg = g_ming_part[0][idx];
#pragma unroll
        for (int s = 1; s < PBLK; s++) vg = fminf(vg, g_ming_part[s][idx]);
        acc += (double)vp + (double)vg;
    }
    sh[threadIdx.x] = acc;
    __syncthreads();
    for (int s = F1T / 2; s > 0; s >>= 1) {
        if (threadIdx.x < s) sh[threadIdx.x] += sh[threadIdx.x + s];
        __syncthreads();
    }
    if (threadIdx.x == 0) g_partial[blockIdx.x] = sh[0];
}

__global__ void chamfer_finalize2(float* __restrict__ out) {
    __shared__ double sh[F1BLOCKS];
    sh[threadIdx.x] = g_partial[threadIdx.x];
    __syncthreads();
    for (int s = F1BLOCKS / 2; s > 0; s >>= 1) {
        if (threadIdx.x < s) sh[threadIdx.x] += sh[threadIdx.x + s];
        __syncthreads();
    }
    if (threadIdx.x == 0)
        out[0] = (float)(sh[0] / ((double)NN * (double)BB));
}

extern "C" void kernel_launch(void* const* d_in, const int* in_sizes, int n_in,
                              void* d_out, int out_size) {
    const float* pred = (const float*)d_in[0];
    const float* gt   = (const float*)d_in[1];
    float* out = (float*)d_out;

    dim3 grid(BB * PBLK, SPLIT_G);
    chamfer_main<<<grid, THREADS>>>(pred, gt);
    chamfer_finalize1<<<F1BLOCKS, F1T>>>();
    chamfer_finalize2<<<1, F1BLOCKS>>>(out);
}

// round 10
// speedup vs baseline: 2.9817x; 1.0225x over previous
#include <cuda_runtime.h>

// Chamfer distance, B=8, Np=8192, Ng=8192, D=3.
// f32x2 packed FMAs; +1.0 bias -> positive distances -> raw-bit s32 redux.
// Software-pipelined: redux/STS for pair i overlaps FMA work for pair i+1.

#define BB 8
#define NN 8192
#define THREADS 128
#define RR 8                        // pred points per thread (4 packed pairs)
#define RP (RR / 2)
#define TILE_P (THREADS * RR)       // 1024 pred points per block
#define PBLK (NN / TILE_P)          // 8
#define SPLIT_G 16
#define CHUNK_G (NN / SPLIT_G)      // 512 gt points per block
#define NWARP (THREADS / 32)        // 4

__device__ float g_minp_part[SPLIT_G][BB * NN];
__device__ float g_ming_part[PBLK][BB * NN];
__device__ double g_partial[128];

__device__ __forceinline__ unsigned long long add2(unsigned long long a, unsigned long long b) {
    unsigned long long d;
    asm("add.rn.f32x2 %0, %1, %2;" : "=l"(d) : "l"(a), "l"(b));
    return d;
}
__device__ __forceinline__ unsigned long long fma2(unsigned long long a, unsigned long long b,
                                                   unsigned long long c) {
    unsigned long long d;
    asm("fma.rn.f32x2 %0, %1, %2, %3;" : "=l"(d) : "l"(a), "l"(b), "l"(c));
    return d;
}
__device__ __forceinline__ unsigned long long pack2(float lo, float hi) {
    unsigned long long d;
    asm("mov.b64 %0, {%1, %2};" : "=l"(d) : "f"(lo), "f"(hi));
    return d;
}
__device__ __forceinline__ unsigned long long pack2i(int lo, int hi) {
    unsigned long long d;
    asm("mov.b64 %0, {%1, %2};" : "=l"(d) : "r"(lo), "r"(hi));
    return d;
}
__device__ __forceinline__ void unpack2f(float& lo, float& hi, unsigned long long a) {
    asm("mov.b64 {%0, %1}, %2;" : "=f"(lo), "=f"(hi) : "l"(a));
}
__device__ __forceinline__ int redux_min_s32(int v) {
    int d;
    asm("redux.sync.min.s32 %0, %1, %2;" : "=r"(d) : "r"(v), "r"(0xFFFFFFFFu));
    return d;
}

__global__ __launch_bounds__(THREADS, 8)
void chamfer_main(const float* __restrict__ pred, const float* __restrict__ gt) {
    const int bs = blockIdx.x;          // [0, BB*PBLK)
    const int b  = bs / PBLK;
    const int pb = bs % PBLK;
    const int gs = blockIdx.y;          // [0, SPLIT_G)
    const int tid = threadIdx.x;
    const int warp = tid >> 5;

    __shared__ float4 shga[CHUNK_G];    // {-2x,-2x,-2y,-2y}
    __shared__ float4 shgb[CHUNK_G];    // {-2z,-2z,g2+1,g2+1}
    __shared__ unsigned long long shminw2[NWARP][CHUNK_G / 2];

    const float* gtb = gt + ((long)b * NN + (long)gs * CHUNK_G) * 3;
    for (int j = tid; j < CHUNK_G; j += THREADS) {
        float x = gtb[j * 3 + 0];
        float y = gtb[j * 3 + 1];
        float z = gtb[j * 3 + 2];
        float nx = -2.0f * x, ny = -2.0f * y, nz = -2.0f * z;
        float w = x * x + y * y + z * z + 1.0f;
        shga[j] = make_float4(nx, nx, ny, ny);
        shgb[j] = make_float4(nz, nz, w, w);
    }

    unsigned long long px2[RP], py2[RP], pz2[RP], pw2[RP];
    float mp[RR];
    const float* pbase = pred + ((long)b * NN + (long)pb * TILE_P) * 3;
#pragma unroll
    for (int p = 0; p < RP; p++) {
        int i0 = (2 * p) * THREADS + tid;
        int i1 = (2 * p + 1) * THREADS + tid;
        float x0 = pbase[i0 * 3 + 0], y0 = pbase[i0 * 3 + 1], z0 = pbase[i0 * 3 + 2];
        float x1 = pbase[i1 * 3 + 0], y1 = pbase[i1 * 3 + 1], z1 = pbase[i1 * 3 + 2];
        px2[p] = pack2(x0, x1);
        py2[p] = pack2(y0, y1);
        pz2[p] = pack2(z0, z1);
        pw2[p] = pack2(x0 * x0 + y0 * y0 + z0 * z0,
                       x1 * x1 + y1 * y1 + z1 * z1);
        mp[2 * p]     = __int_as_float(0x7F800000);
        mp[2 * p + 1] = __int_as_float(0x7F800000);
    }
    __syncthreads();

    const ulonglong2* ga = reinterpret_cast<const ulonglong2*>(shga);
    const ulonglong2* gb = reinterpret_cast<const ulonglong2*>(shgb);

    // Distance + local-tree block for gt pair (j, j+1). Outputs pm0/pm1
    // (pre-redux per-lane mins) and updates mp accumulators.
#define COMPUTE_PAIR(J, PM0, PM1)                                              \
    do {                                                                       \
        ulonglong2 A0 = ga[J],     B0 = gb[J];                                 \
        ulonglong2 A1 = ga[(J) + 1], B1 = gb[(J) + 1];                         \
        float tm0[RP], tm1[RP];                                                \
        _Pragma("unroll")                                                      \
        for (int p = 0; p < RP; p++) {                                         \
            unsigned long long a = add2(pw2[p], B0.y);                         \
            a = fma2(A0.x, px2[p], a);                                         \
            a = fma2(A0.y, py2[p], a);                                         \
            a = fma2(B0.x, pz2[p], a);                                         \
            float lo, hi;                                                      \
            unpack2f(lo, hi, a);                                               \
            mp[2 * p]     = fminf(mp[2 * p], lo);                              \
            mp[2 * p + 1] = fminf(mp[2 * p + 1], hi);                          \
            tm0[p] = fminf(lo, hi);                                            \
            unsigned long long c = add2(pw2[p], B1.y);                         \
            c = fma2(A1.x, px2[p], c);                                         \
            c = fma2(A1.y, py2[p], c);                                         \
            c = fma2(B1.x, pz2[p], c);                                         \
            unpack2f(lo, hi, c);                                               \
            mp[2 * p]     = fminf(mp[2 * p], lo);                              \
            mp[2 * p + 1] = fminf(mp[2 * p + 1], hi);                          \
            tm1[p] = fminf(lo, hi);                                            \
        }                                                                      \
        PM0 = fminf(fminf(tm0[0], tm0[1]), fminf(tm0[2], tm0[3]));             \
        PM1 = fminf(fminf(tm1[0], tm1[1]), fminf(tm1[2], tm1[3]));             \
    } while (0)

    // Software pipeline: redux/STS of pair i overlap compute of pair i+1.
    float pm0, pm1;
    COMPUTE_PAIR(0, pm0, pm1);
    for (int j = 2; j < CHUNK_G; j += 2) {
        int r0 = redux_min_s32(__float_as_int(pm0));
        int r1 = redux_min_s32(__float_as_int(pm1));
        COMPUTE_PAIR(j, pm0, pm1);                 // independent work hides redux
        shminw2[warp][(j >> 1) - 1] = pack2i(r0, r1);
    }
    {
        int r0 = redux_min_s32(__float_as_int(pm0));
        int r1 = redux_min_s32(__float_as_int(pm1));
        shminw2[warp][CHUNK_G / 2 - 1] = pack2i(r0, r1);
    }
#undef COMPUTE_PAIR
    __syncthreads();

    // gt-direction publish: combine warps (int min on positive bits), unbias.
    const int* sw = reinterpret_cast<const int*>(shminw2);
    float* gm = g_ming_part[pb] + (long)b * NN + (long)gs * CHUNK_G;
    for (int j = tid; j < CHUNK_G; j += THREADS) {
        int v = sw[j];
#pragma unroll
        for (int w = 1; w < NWARP; w++) v = min(v, sw[w * CHUNK_G + j]);
        gm[j] = __int_as_float(v) - 1.0f;
    }

    // pred-direction publish: unbias, plain store.
    float* pm = g_minp_part[gs] + (long)b * NN + (long)pb * TILE_P;
#pragma unroll
    for (int r = 0; r < RR; r++)
        pm[r * THREADS + tid] = mp[r] - 1.0f;
}

#define F1BLOCKS 128
#define F1T 256
#define PTS_PER_BLK (BB * NN / F1BLOCKS)   // 512

__global__ __launch_bounds__(F1T)
void chamfer_finalize1() {
    __shared__ double sh[F1T];
    const int base = blockIdx.x * PTS_PER_BLK;
    double acc = 0.0;
    for (int i = threadIdx.x; i < PTS_PER_BLK; i += F1T) {
        int idx = base + i;
        float vp = g_minp_part[0][idx];
#pragma unroll
        for (int s = 1; s < SPLIT_G; s++) vp = fminf(vp, g_minp_part[s][idx]);
        float vg = g_ming_part[0][idx];
#pragma unroll
        for (int s = 1; s < PBLK; s++) vg = fminf(vg, g_ming_part[s][idx]);
        acc += (double)vp + (double)vg;
    }
    sh[threadIdx.x] = acc;
    __syncthreads();
    for (int s = F1T / 2; s > 0; s >>= 1) {
        if (threadIdx.x < s) sh[threadIdx.x] += sh[threadIdx.x + s];
        __syncthreads();
    }
    if (threadIdx.x == 0) g_partial[blockIdx.x] = sh[0];
}

__global__ void chamfer_finalize2(float* __restrict__ out) {
    __shared__ double sh[F1BLOCKS];
    sh[threadIdx.x] = g_partial[threadIdx.x];
    __syncthreads();
    for (int s = F1BLOCKS / 2; s > 0; s >>= 1) {
        if (threadIdx.x < s) sh[threadIdx.x] += sh[threadIdx.x + s];
        __syncthreads();
    }
    if (threadIdx.x == 0)
        out[0] = (float)(sh[0] / ((double)NN * (double)BB));
}

extern "C" void kernel_launch(void* const* d_in, const int* in_sizes, int n_in,
                              void* d_out, int out_size) {
    const float* pred = (const float*)d_in[0];
    const float* gt   = (const float*)d_in[1];
    float* out = (float*)d_out;

    dim3 grid(BB * PBLK, SPLIT_G);
    chamfer_main<<<grid, THREADS>>>(pred, gt);
    chamfer_finalize1<<<F1BLOCKS, F1T>>>();
    chamfer_finalize2<<<1, F1BLOCKS>>>(out);
}

// round 11
// speedup vs baseline: 3.2165x; 1.0788x over previous
#include <cuda_runtime.h>

// Chamfer distance, B=8, Np=8192, Ng=8192, D=3.
// f32x2 packed FMAs; +1.0 bias -> positive distances -> raw-bit s32 redux.
// R11 probe: launch_bounds(128,7) -> 73-reg budget (was 64) to free ptxas
// scheduling; still single wave (1024 blocks <= 148*7=1036).

#define BB 8
#define NN 8192
#define THREADS 128
#define RR 8                        // pred points per thread (4 packed pairs)
#define RP (RR / 2)
#define TILE_P (THREADS * RR)       // 1024 pred points per block
#define PBLK (NN / TILE_P)          // 8
#define SPLIT_G 16
#define CHUNK_G (NN / SPLIT_G)      // 512 gt points per block
#define NWARP (THREADS / 32)        // 4

__device__ float g_minp_part[SPLIT_G][BB * NN];
__device__ float g_ming_part[PBLK][BB * NN];
__device__ double g_partial[128];

__device__ __forceinline__ unsigned long long add2(unsigned long long a, unsigned long long b) {
    unsigned long long d;
    asm("add.rn.f32x2 %0, %1, %2;" : "=l"(d) : "l"(a), "l"(b));
    return d;
}
__device__ __forceinline__ unsigned long long fma2(unsigned long long a, unsigned long long b,
                                                   unsigned long long c) {
    unsigned long long d;
    asm("fma.rn.f32x2 %0, %1, %2, %3;" : "=l"(d) : "l"(a), "l"(b), "l"(c));
    return d;
}
__device__ __forceinline__ unsigned long long pack2(float lo, float hi) {
    unsigned long long d;
    asm("mov.b64 %0, {%1, %2};" : "=l"(d) : "f"(lo), "f"(hi));
    return d;
}
__device__ __forceinline__ unsigned long long pack2i(int lo, int hi) {
    unsigned long long d;
    asm("mov.b64 %0, {%1, %2};" : "=l"(d) : "r"(lo), "r"(hi));
    return d;
}
__device__ __forceinline__ void unpack2f(float& lo, float& hi, unsigned long long a) {
    asm("mov.b64 {%0, %1}, %2;" : "=f"(lo), "=f"(hi) : "l"(a));
}
__device__ __forceinline__ int redux_min_s32(int v) {
    int d;
    asm("redux.sync.min.s32 %0, %1, %2;" : "=r"(d) : "r"(v), "r"(0xFFFFFFFFu));
    return d;
}

__global__ __launch_bounds__(THREADS, 7)
void chamfer_main(const float* __restrict__ pred, const float* __restrict__ gt) {
    const int bs = blockIdx.x;          // [0, BB*PBLK)
    const int b  = bs / PBLK;
    const int pb = bs % PBLK;
    const int gs = blockIdx.y;          // [0, SPLIT_G)
    const int tid = threadIdx.x;
    const int warp = tid >> 5;

    __shared__ float4 shga[CHUNK_G];    // {-2x,-2x,-2y,-2y}
    __shared__ float4 shgb[CHUNK_G];    // {-2z,-2z,g2+1,g2+1}
    __shared__ unsigned long long shminw2[NWARP][CHUNK_G / 2];

    const float* gtb = gt + ((long)b * NN + (long)gs * CHUNK_G) * 3;
    for (int j = tid; j < CHUNK_G; j += THREADS) {
        float x = gtb[j * 3 + 0];
        float y = gtb[j * 3 + 1];
        float z = gtb[j * 3 + 2];
        float nx = -2.0f * x, ny = -2.0f * y, nz = -2.0f * z;
        float w = x * x + y * y + z * z + 1.0f;
        shga[j] = make_float4(nx, nx, ny, ny);
        shgb[j] = make_float4(nz, nz, w, w);
    }

    unsigned long long px2[RP], py2[RP], pz2[RP], pw2[RP];
    float mp[RR];
    const float* pbase = pred + ((long)b * NN + (long)pb * TILE_P) * 3;
#pragma unroll
    for (int p = 0; p < RP; p++) {
        int i0 = (2 * p) * THREADS + tid;
        int i1 = (2 * p + 1) * THREADS + tid;
        float x0 = pbase[i0 * 3 + 0], y0 = pbase[i0 * 3 + 1], z0 = pbase[i0 * 3 + 2];
        float x1 = pbase[i1 * 3 + 0], y1 = pbase[i1 * 3 + 1], z1 = pbase[i1 * 3 + 2];
        px2[p] = pack2(x0, x1);
        py2[p] = pack2(y0, y1);
        pz2[p] = pack2(z0, z1);
        pw2[p] = pack2(x0 * x0 + y0 * y0 + z0 * z0,
                       x1 * x1 + y1 * y1 + z1 * z1);
        mp[2 * p]     = __int_as_float(0x7F800000);
        mp[2 * p + 1] = __int_as_float(0x7F800000);
    }
    __syncthreads();

    const ulonglong2* ga = reinterpret_cast<const ulonglong2*>(shga);
    const ulonglong2* gb = reinterpret_cast<const ulonglong2*>(shgb);

#define COMPUTE_PAIR(J, PM0, PM1)                                              \
    do {                                                                       \
        ulonglong2 A0 = ga[J],     B0 = gb[J];                                 \
        ulonglong2 A1 = ga[(J) + 1], B1 = gb[(J) + 1];                         \
        float tm0[RP], tm1[RP];                                                \
        _Pragma("unroll")                                                      \
        for (int p = 0; p < RP; p++) {                                         \
            unsigned long long a = add2(pw2[p], B0.y);                         \
            a = fma2(A0.x, px2[p], a);                                         \
            a = fma2(A0.y, py2[p], a);                                         \
            a = fma2(B0.x, pz2[p], a);                                         \
            float lo, hi;                                                      \
            unpack2f(lo, hi, a);                                               \
            mp[2 * p]     = fminf(mp[2 * p], lo);                              \
            mp[2 * p + 1] = fminf(mp[2 * p + 1], hi);                          \
            tm0[p] = fminf(lo, hi);                                            \
            unsigned long long c = add2(pw2[p], B1.y);                         \
            c = fma2(A1.x, px2[p], c);                                         \
            c = fma2(A1.y, py2[p], c);                                         \
            c = fma2(B1.x, pz2[p], c);                                         \
            unpack2f(lo, hi, c);                                               \
            mp[2 * p]     = fminf(mp[2 * p], lo);                              \
            mp[2 * p + 1] = fminf(mp[2 * p + 1], hi);                          \
            tm1[p] = fminf(lo, hi);                                            \
        }                                                                      \
        PM0 = fminf(fminf(tm0[0], tm0[1]), fminf(tm0[2], tm0[3]));             \
        PM1 = fminf(fminf(tm1[0], tm1[1]), fminf(tm1[2], tm1[3]));             \
    } while (0)

    // Software pipeline: redux/STS of pair i overlap compute of pair i+1.
    float pm0, pm1;
    COMPUTE_PAIR(0, pm0, pm1);
    for (int j = 2; j < CHUNK_G; j += 2) {
        int r0 = redux_min_s32(__float_as_int(pm0));
        int r1 = redux_min_s32(__float_as_int(pm1));
        COMPUTE_PAIR(j, pm0, pm1);
        shminw2[warp][(j >> 1) - 1] = pack2i(r0, r1);
    }
    {
        int r0 = redux_min_s32(__float_as_int(pm0));
        int r1 = redux_min_s32(__float_as_int(pm1));
        shminw2[warp][CHUNK_G / 2 - 1] = pack2i(r0, r1);
    }
#undef COMPUTE_PAIR
    __syncthreads();

    const int* sw = reinterpret_cast<const int*>(shminw2);
    float* gm = g_ming_part[pb] + (long)b * NN + (long)gs * CHUNK_G;
    for (int j = tid; j < CHUNK_G; j += THREADS) {
        int v = sw[j];
#pragma unroll
        for (int w = 1; w < NWARP; w++) v = min(v, sw[w * CHUNK_G + j]);
        gm[j] = __int_as_float(v) - 1.0f;
    }

    float* pm = g_minp_part[gs] + (long)b * NN + (long)pb * TILE_P;
#pragma unroll
    for (int r = 0; r < RR; r++)
        pm[r * THREADS + tid] = mp[r] - 1.0f;
}

#define F1BLOCKS 128
#define F1T 256
#define PTS_PER_BLK (BB * NN / F1BLOCKS)   // 512

__global__ __launch_bounds__(F1T)
void chamfer_finalize1() {
    __shared__ double sh[F1T];
    const int base = blockIdx.x * PTS_PER_BLK;
    double acc = 0.0;
    for (int i = threadIdx.x; i < PTS_PER_BLK; i += F1T) {
        int idx = base + i;
        float vp = g_minp_part[0][idx];
#pragma unroll
        for (int s = 1; s < SPLIT_G; s++) vp = fminf(vp, g_minp_part[s][idx]);
        float vg = g_ming_part[0][idx];
#pragma unroll
        for (int s = 1; s < PBLK; s++) vg = fminf(vg, g_ming_part[s][idx]);
        acc += (double)vp + (double)vg;
    }
    sh[threadIdx.x] = acc;
    __syncthreads();
    for (int s = F1T / 2; s > 0; s >>= 1) {
        if (threadIdx.x < s) sh[threadIdx.x] += sh[threadIdx.x + s];
        __syncthreads();
    }
    if (threadIdx.x == 0) g_partial[blockIdx.x] = sh[0];
}

__global__ void chamfer_finalize2(float* __restrict__ out) {
    __shared__ double sh[F1BLOCKS];
    sh[threadIdx.x] = g_partial[threadIdx.x];
    __syncthreads();
    for (int s = F1BLOCKS / 2; s > 0; s >>= 1) {
        if (threadIdx.x < s) sh[threadIdx.x] += sh[threadIdx.x + s];
        __syncthreads();
    }
    if (threadIdx.x == 0)
        out[0] = (float)(sh[0] / ((double)NN * (double)BB));
}

extern "C" void kernel_launch(void* const* d_in, const int* in_sizes, int n_in,
                              void* d_out, int out_size) {
    const float* pred = (const float*)d_in[0];
    const float* gt   = (const float*)d_in[1];
    float* out = (float*)d_out;

    dim3 grid(BB * PBLK, SPLIT_G);
    chamfer_main<<<grid, THREADS>>>(pred, gt);
    chamfer_finalize1<<<F1BLOCKS, F1T>>>();
    chamfer_finalize2<<<1, F1BLOCKS>>>(out);
}

// round 12
// speedup vs baseline: 3.2229x; 1.0020x over previous
#include <cuda_runtime.h>

// Chamfer distance, B=8, Np=8192, Ng=8192, D=3.
// f32x2 packed FMAs; +1.0 bias -> positive distances -> raw-bit s32 redux.
// Pipelined (redux/STS of pair i overlap compute of i+1) + unroll 2 so ptxas
// interleaves two independent streams. launch_bounds(128,7): 73-reg budget,
// single wave (1024 blocks <= 148*7=1036).

#define BB 8
#define NN 8192
#define THREADS 128
#define RR 8                        // pred points per thread (4 packed pairs)
#define RP (RR / 2)
#define TILE_P (THREADS * RR)       // 1024 pred points per block
#define PBLK (NN / TILE_P)          // 8
#define SPLIT_G 16
#define CHUNK_G (NN / SPLIT_G)      // 512 gt points per block
#define NWARP (THREADS / 32)        // 4

__device__ float g_minp_part[SPLIT_G][BB * NN];
__device__ float g_ming_part[PBLK][BB * NN];
__device__ double g_partial[128];

__device__ __forceinline__ unsigned long long add2(unsigned long long a, unsigned long long b) {
    unsigned long long d;
    asm("add.rn.f32x2 %0, %1, %2;" : "=l"(d) : "l"(a), "l"(b));
    return d;
}
__device__ __forceinline__ unsigned long long fma2(unsigned long long a, unsigned long long b,
                                                   unsigned long long c) {
    unsigned long long d;
    asm("fma.rn.f32x2 %0, %1, %2, %3;" : "=l"(d) : "l"(a), "l"(b), "l"(c));
    return d;
}
__device__ __forceinline__ unsigned long long pack2(float lo, float hi) {
    unsigned long long d;
    asm("mov.b64 %0, {%1, %2};" : "=l"(d) : "f"(lo), "f"(hi));
    return d;
}
__device__ __forceinline__ unsigned long long pack2i(int lo, int hi) {
    unsigned long long d;
    asm("mov.b64 %0, {%1, %2};" : "=l"(d) : "r"(lo), "r"(hi));
    return d;
}
__device__ __forceinline__ void unpack2f(float& lo, float& hi, unsigned long long a) {
    asm("mov.b64 {%0, %1}, %2;" : "=f"(lo), "=f"(hi) : "l"(a));
}
__device__ __forceinline__ int redux_min_s32(int v) {
    int d;
    asm("redux.sync.min.s32 %0, %1, %2;" : "=r"(d) : "r"(v), "r"(0xFFFFFFFFu));
    return d;
}

__global__ __launch_bounds__(THREADS, 7)
void chamfer_main(const float* __restrict__ pred, const float* __restrict__ gt) {
    const int bs = blockIdx.x;          // [0, BB*PBLK)
    const int b  = bs / PBLK;
    const int pb = bs % PBLK;
    const int gs = blockIdx.y;          // [0, SPLIT_G)
    const int tid = threadIdx.x;
    const int warp = tid >> 5;

    __shared__ float4 shga[CHUNK_G];    // {-2x,-2x,-2y,-2y}
    __shared__ float4 shgb[CHUNK_G];    // {-2z,-2z,g2+1,g2+1}
    __shared__ unsigned long long shminw2[NWARP][CHUNK_G / 2];

    const float* gtb = gt + ((long)b * NN + (long)gs * CHUNK_G) * 3;
    for (int j = tid; j < CHUNK_G; j += THREADS) {
        float x = gtb[j * 3 + 0];
        float y = gtb[j * 3 + 1];
        float z = gtb[j * 3 + 2];
        float nx = -2.0f * x, ny = -2.0f * y, nz = -2.0f * z;
        float w = x * x + y * y + z * z + 1.0f;
        shga[j] = make_float4(nx, nx, ny, ny);
        shgb[j] = make_float4(nz, nz, w, w);
    }

    unsigned long long px2[RP], py2[RP], pz2[RP], pw2[RP];
    float mp[RR];
    const float* pbase = pred + ((long)b * NN + (long)pb * TILE_P) * 3;
#pragma unroll
    for (int p = 0; p < RP; p++) {
        int i0 = (2 * p) * THREADS + tid;
        int i1 = (2 * p + 1) * THREADS + tid;
        float x0 = pbase[i0 * 3 + 0], y0 = pbase[i0 * 3 + 1], z0 = pbase[i0 * 3 + 2];
        float x1 = pbase[i1 * 3 + 0], y1 = pbase[i1 * 3 + 1], z1 = pbase[i1 * 3 + 2];
        px2[p] = pack2(x0, x1);
        py2[p] = pack2(y0, y1);
        pz2[p] = pack2(z0, z1);
        pw2[p] = pack2(x0 * x0 + y0 * y0 + z0 * z0,
                       x1 * x1 + y1 * y1 + z1 * z1);
        mp[2 * p]     = __int_as_float(0x7F800000);
        mp[2 * p + 1] = __int_as_float(0x7F800000);
    }
    __syncthreads();

    const ulonglong2* ga = reinterpret_cast<const ulonglong2*>(shga);
    const ulonglong2* gb = reinterpret_cast<const ulonglong2*>(shgb);

#define COMPUTE_PAIR(J, PM0, PM1)                                              \
    do {                                                                       \
        ulonglong2 A0 = ga[J],     B0 = gb[J];                                 \
        ulonglong2 A1 = ga[(J) + 1], B1 = gb[(J) + 1];                         \
        float tm0[RP], tm1[RP];                                                \
        _Pragma("unroll")                                                      \
        for (int p = 0; p < RP; p++) {                                         \
            unsigned long long a = add2(pw2[p], B0.y);                         \
            a = fma2(A0.x, px2[p], a);                                         \
            a = fma2(A0.y, py2[p], a);                                         \
            a = fma2(B0.x, pz2[p], a);                                         \
            float lo, hi;                                                      \
            unpack2f(lo, hi, a);                                               \
            mp[2 * p]     = fminf(mp[2 * p], lo);                              \
            mp[2 * p + 1] = fminf(mp[2 * p + 1], hi);                          \
            tm0[p] = fminf(lo, hi);                                            \
            unsigned long long c = add2(pw2[p], B1.y);                         \
            c = fma2(A1.x, px2[p], c);                                         \
            c = fma2(A1.y, py2[p], c);                                         \
            c = fma2(B1.x, pz2[p], c);                                         \
            unpack2f(lo, hi, c);                                               \
            mp[2 * p]     = fminf(mp[2 * p], lo);                              \
            mp[2 * p + 1] = fminf(mp[2 * p + 1], hi);                          \
            tm1[p] = fminf(lo, hi);                                            \
        }                                                                      \
        PM0 = fminf(fminf(tm0[0], tm0[1]), fminf(tm0[2], tm0[3]));             \
        PM1 = fminf(fminf(tm1[0], tm1[1]), fminf(tm1[2], tm1[3]));             \
    } while (0)

    // Software pipeline: redux/STS of pair i overlap compute of pair i+1.
    // unroll 2: two independent streams for ptxas to interleave.
    float pm0, pm1;
    COMPUTE_PAIR(0, pm0, pm1);
#pragma unroll 2
    for (int j = 2; j < CHUNK_G; j += 2) {
        int r0 = redux_min_s32(__float_as_int(pm0));
        int r1 = redux_min_s32(__float_as_int(pm1));
        COMPUTE_PAIR(j, pm0, pm1);
        shminw2[warp][(j >> 1) - 1] = pack2i(r0, r1);
    }
    {
        int r0 = redux_min_s32(__float_as_int(pm0));
        int r1 = redux_min_s32(__float_as_int(pm1));
        shminw2[warp][CHUNK_G / 2 - 1] = pack2i(r0, r1);
    }
#undef COMPUTE_PAIR
    __syncthreads();

    const int* sw = reinterpret_cast<const int*>(shminw2);
    float* gm = g_ming_part[pb] + (long)b * NN + (long)gs * CHUNK_G;
    for (int j = tid; j < CHUNK_G; j += THREADS) {
        int v = sw[j];
#pragma unroll
        for (int w = 1; w < NWARP; w++) v = min(v, sw[w * CHUNK_G + j]);
        gm[j] = __int_as_float(v) - 1.0f;
    }

    float* pm = g_minp_part[gs] + (long)b * NN + (long)pb * TILE_P;
#pragma unroll
    for (int r = 0; r < RR; r++)
        pm[r * THREADS + tid] = mp[r] - 1.0f;
}

#define F1BLOCKS 128
#define F1T 256
#define PTS_PER_BLK (BB * NN / F1BLOCKS)   // 512

__global__ __launch_bounds__(F1T)
void chamfer_finalize1() {
    __shared__ double sh[F1T];
    const int base = blockIdx.x * PTS_PER_BLK;
    double acc = 0.0;
    for (int i = threadIdx.x; i < PTS_PER_BLK; i += F1T) {
        int idx = base + i;
        float vp = g_minp_part[0][idx];
#pragma unroll
        for (int s = 1; s < SPLIT_G; s++) vp = fminf(vp, g_minp_part[s][idx]);
        float vg = g_ming_part[0][idx];
#pragma unroll
        for (int s = 1; s < PBLK; s++) vg = fminf(vg, g_ming_part[s][idx]);
        acc += (double)vp + (double)vg;
    }
    sh[threadIdx.x] = acc;
    __syncthreads();
    for (int s = F1T / 2; s > 0; s >>= 1) {
        if (threadIdx.x < s) sh[threadIdx.x] += sh[threadIdx.x + s];
        __syncthreads();
    }
    if (threadIdx.x == 0) g_partial[blockIdx.x] = sh[0];
}

__global__ void chamfer_finalize2(float* __restrict__ out) {
    __shared__ double sh[F1BLOCKS];
    sh[threadIdx.x] = g_partial[threadIdx.x];
    __syncthreads();
    for (int s = F1BLOCKS / 2; s > 0; s >>= 1) {
        if (threadIdx.x < s) sh[threadIdx.x] += sh[threadIdx.x + s];
        __syncthreads();
    }
    if (threadIdx.x == 0)
        out[0] = (float)(sh[0] / ((double)NN * (double)BB));
}

extern "C" void kernel_launch(void* const* d_in, const int* in_sizes, int n_in,
                              void* d_out, int out_size) {
    const float* pred = (const float*)d_in[0];
    const float* gt   = (const float*)d_in[1];
    float* out = (float*)d_out;

    dim3 grid(BB * PBLK, SPLIT_G);
    chamfer_main<<<grid, THREADS>>>(pred, gt);
    chamfer_finalize1<<<F1BLOCKS, F1T>>>();
    chamfer_finalize2<<<1, F1BLOCKS>>>(out);
}